// round 1
// baseline (speedup 1.0000x reference)
#include <cuda_runtime.h>
#include <cuda_bf16.h>

// Problem constants
#define B_SZ   2
#define S_SZ   2048
#define DM     1024
#define NH     16
#define DK     64
#define BS     (B_SZ * S_SZ)          // 4096 rows

// Scratch (no cudaMalloc allowed -> device globals)
__device__ float g_Q[BS * DM];
__device__ float g_K[BS * DM];
__device__ float g_V[BS * DM];
__device__ float g_O[BS * DM];
__device__ float g_M[B_SZ * NH * DK * DK];   // per (b,h): (K^T V)/8, 64x64

// ---------------------------------------------------------------------------
// GEMM: C[M,N] = A[M,K] * W[N,K]^T    (both row-major, K contiguous: "NT")
// BM=BN=128, BK=8, 256 threads, 8x8 per thread.
// ---------------------------------------------------------------------------
#define BM 128
#define BN 128
#define BK 8
#define TM 8
#define TN 8

__global__ __launch_bounds__(256, 2)
void sgemm_nt(const float* __restrict__ A, const float* __restrict__ W,
              float* __restrict__ C, int M, int N, int K)
{
    __shared__ float As[BK][BM];
    __shared__ float Ws[BK][BN];

    const int tid = threadIdx.x;
    const int bm = blockIdx.y * BM;
    const int bn = blockIdx.x * BN;

    // global-load mapping: 128 rows x 8 cols = 1024 floats = 256 float4
    const int lrow = tid >> 1;           // 0..127
    const int lcol = (tid & 1) * 4;      // 0 or 4

    const int ty = tid >> 4;             // 0..15 -> row block
    const int tx = tid & 15;             // 0..15 -> col block

    const float* Ap = A + (size_t)(bm + lrow) * K + lcol;
    const float* Wp = W + (size_t)(bn + lrow) * K + lcol;

    float acc[TM][TN];
#pragma unroll
    for (int i = 0; i < TM; ++i)
#pragma unroll
        for (int j = 0; j < TN; ++j) acc[i][j] = 0.0f;

    for (int k0 = 0; k0 < K; k0 += BK) {
        float4 av = *reinterpret_cast<const float4*>(Ap + k0);
        float4 wv = *reinterpret_cast<const float4*>(Wp + k0);
        As[lcol + 0][lrow] = av.x;
        As[lcol + 1][lrow] = av.y;
        As[lcol + 2][lrow] = av.z;
        As[lcol + 3][lrow] = av.w;
        Ws[lcol + 0][lrow] = wv.x;
        Ws[lcol + 1][lrow] = wv.y;
        Ws[lcol + 2][lrow] = wv.z;
        Ws[lcol + 3][lrow] = wv.w;
        __syncthreads();

#pragma unroll
        for (int kk = 0; kk < BK; ++kk) {
            float4 a0 = *reinterpret_cast<const float4*>(&As[kk][ty * TM]);
            float4 a1 = *reinterpret_cast<const float4*>(&As[kk][ty * TM + 4]);
            float4 b0 = *reinterpret_cast<const float4*>(&Ws[kk][tx * TN]);
            float4 b1 = *reinterpret_cast<const float4*>(&Ws[kk][tx * TN + 4]);
            float a[TM] = {a0.x, a0.y, a0.z, a0.w, a1.x, a1.y, a1.z, a1.w};
            float b[TN] = {b0.x, b0.y, b0.z, b0.w, b1.x, b1.y, b1.z, b1.w};
#pragma unroll
            for (int i = 0; i < TM; ++i)
#pragma unroll
                for (int j = 0; j < TN; ++j)
                    acc[i][j] = fmaf(a[i], b[j], acc[i][j]);
        }
        __syncthreads();
    }

    float* Cp = C + (size_t)(bm + ty * TM) * N + bn + tx * TN;
#pragma unroll
    for (int i = 0; i < TM; ++i) {
        float4 v0 = {acc[i][0], acc[i][1], acc[i][2], acc[i][3]};
        float4 v1 = {acc[i][4], acc[i][5], acc[i][6], acc[i][7]};
        *reinterpret_cast<float4*>(Cp + (size_t)i * N)     = v0;
        *reinterpret_cast<float4*>(Cp + (size_t)i * N + 4) = v1;
    }
}

// ---------------------------------------------------------------------------
// Kernel 2: M[bh][d1][d2] = (1/8) * sum_s K[b,s,h,d1] * V[b,s,h,d2]
// one block per (b,h), 256 threads, 4x4 outputs per thread over a 64x64 tile
// ---------------------------------------------------------------------------
__global__ __launch_bounds__(256)
void ktv_kernel(const float* __restrict__ Km, const float* __restrict__ Vm,
                float* __restrict__ Mh)
{
    const int bh = blockIdx.x;           // 0..31
    const int b = bh >> 4, h = bh & 15;
    const float* Kb = Km + (size_t)b * S_SZ * DM + h * DK;
    const float* Vb = Vm + (size_t)b * S_SZ * DM + h * DK;

    __shared__ float Ks[32][DK];
    __shared__ float Vs[32][DK];

    const int tid = threadIdx.x;
    const int tx = tid & 15;             // d2 block
    const int ty = tid >> 4;             // d1 block

    float acc[4][4];
#pragma unroll
    for (int i = 0; i < 4; ++i)
#pragma unroll
        for (int j = 0; j < 4; ++j) acc[i][j] = 0.0f;

    for (int s0 = 0; s0 < S_SZ; s0 += 32) {
        // 32 rows x 64 floats = 512 float4, 256 threads -> 2 each
#pragma unroll
        for (int i = 0; i < 2; ++i) {
            int idx = tid + i * 256;       // 0..511
            int r = idx >> 4;
            int c = (idx & 15) * 4;
            *reinterpret_cast<float4*>(&Ks[r][c]) =
                *reinterpret_cast<const float4*>(&Kb[(size_t)(s0 + r) * DM + c]);
            *reinterpret_cast<float4*>(&Vs[r][c]) =
                *reinterpret_cast<const float4*>(&Vb[(size_t)(s0 + r) * DM + c]);
        }
        __syncthreads();
#pragma unroll 8
        for (int s = 0; s < 32; ++s) {
            float kv[4], vv[4];
#pragma unroll
            for (int i = 0; i < 4; ++i) kv[i] = Ks[s][ty * 4 + i];
#pragma unroll
            for (int j = 0; j < 4; ++j) vv[j] = Vs[s][tx * 4 + j];
#pragma unroll
            for (int i = 0; i < 4; ++i)
#pragma unroll
                for (int j = 0; j < 4; ++j)
                    acc[i][j] = fmaf(kv[i], vv[j], acc[i][j]);
        }
        __syncthreads();
    }

    float* Mp = Mh + (size_t)bh * DK * DK;
#pragma unroll
    for (int i = 0; i < 4; ++i)
#pragma unroll
        for (int j = 0; j < 4; ++j)
            Mp[(ty * 4 + i) * DK + tx * 4 + j] = acc[i][j] * 0.125f;
}

// ---------------------------------------------------------------------------
// Kernel 3: O[b,s,h*64+d2] = sum_d1 Q[b,s,h*64+d1] * M[bh][d1][d2]
// grid (s_tiles=32, bh=32), block 256; 64x64 output tile per block
// ---------------------------------------------------------------------------
__global__ __launch_bounds__(256)
void qm_kernel(const float* __restrict__ Q, const float* __restrict__ Mh,
               float* __restrict__ O)
{
    const int bh = blockIdx.y;
    const int b = bh >> 4, h = bh & 15;
    const int s0 = blockIdx.x * 64;

    __shared__ float Ms[DK][DK];
    __shared__ float Qs[64][DK];

    const float* Qb = Q + (size_t)b * S_SZ * DM + h * DK;
    const float* Mp = Mh + (size_t)bh * DK * DK;

    const int tid = threadIdx.x;
    // load M (4096 floats = 1024 float4) and Q tile (same size)
#pragma unroll
    for (int i = 0; i < 4; ++i) {
        int idx = tid + i * 256;      // 0..1023
        int r = idx >> 4;
        int c = (idx & 15) * 4;
        *reinterpret_cast<float4*>(&Ms[r][c]) =
            *reinterpret_cast<const float4*>(&Mp[r * DK + c]);
        *reinterpret_cast<float4*>(&Qs[r][c]) =
            *reinterpret_cast<const float4*>(&Qb[(size_t)(s0 + r) * DM + c]);
    }
    __syncthreads();

    const int tx = tid & 15;          // d2 block
    const int ty = tid >> 4;          // s-row block
    float acc[4][4];
#pragma unroll
    for (int i = 0; i < 4; ++i)
#pragma unroll
        for (int j = 0; j < 4; ++j) acc[i][j] = 0.0f;

#pragma unroll 8
    for (int d = 0; d < DK; ++d) {
        float qv[4], mv[4];
#pragma unroll
        for (int i = 0; i < 4; ++i) qv[i] = Qs[ty * 4 + i][d];
#pragma unroll
        for (int j = 0; j < 4; ++j) mv[j] = Ms[d][tx * 4 + j];
#pragma unroll
        for (int i = 0; i < 4; ++i)
#pragma unroll
            for (int j = 0; j < 4; ++j)
                acc[i][j] = fmaf(qv[i], mv[j], acc[i][j]);
    }

    float* Op = O + (size_t)b * S_SZ * DM + (size_t)s0 * DM + h * DK;
#pragma unroll
    for (int i = 0; i < 4; ++i) {
#pragma unroll
        for (int j = 0; j < 4; ++j) {
            Op[(size_t)(ty * 4 + i) * DM + tx * 4 + j] = acc[i][j];
        }
    }
}

// ---------------------------------------------------------------------------
// Launch
// ---------------------------------------------------------------------------
extern "C" void kernel_launch(void* const* d_in, const int* in_sizes, int n_in,
                              void* d_out, int out_size)
{
    const float* query = (const float*)d_in[0];
    const float* key   = (const float*)d_in[1];
    const float* value = (const float*)d_in[2];
    // d_in[3] = mask (int32) -- unused, the reference discards it
    const float* Wq = (const float*)d_in[4];
    const float* Wk = (const float*)d_in[5];
    const float* Wv = (const float*)d_in[6];
    const float* Wo = (const float*)d_in[7];
    float* out = (float*)d_out;

    float *pQ, *pK, *pV, *pO, *pM;
    cudaGetSymbolAddress((void**)&pQ, g_Q);
    cudaGetSymbolAddress((void**)&pK, g_K);
    cudaGetSymbolAddress((void**)&pV, g_V);
    cudaGetSymbolAddress((void**)&pO, g_O);
    cudaGetSymbolAddress((void**)&pM, g_M);

    dim3 gridP(DM / BN, BS / BM);   // (8, 32)
    dim3 blk(256);

    // Projections: Q = X Wq^T, K = X Wk^T, V = X Wv^T
    sgemm_nt<<<gridP, blk>>>(query, Wq, pQ, BS, DM, DM);
    sgemm_nt<<<gridP, blk>>>(key,   Wk, pK, BS, DM, DM);
    sgemm_nt<<<gridP, blk>>>(value, Wv, pV, BS, DM, DM);

    // M = (K^T V)/8 per (b,h)
    ktv_kernel<<<B_SZ * NH, blk>>>(pK, pV, pM);

    // O = Q M per (b,h)
    dim3 gridQM(S_SZ / 64, B_SZ * NH);   // (32, 32)
    qm_kernel<<<gridQM, blk>>>(pQ, pM, pO);

    // final = O Wo^T
    sgemm_nt<<<gridP, blk>>>(pO, Wo, out, BS, DM, DM);
}

// round 3
// speedup vs baseline: 3.3143x; 3.3143x over previous
#include <cuda_runtime.h>
#include <cuda_bf16.h>
#include <cstdint>

// Problem constants
#define B_SZ   2
#define S_SZ   2048
#define DM     1024
#define NH     16
#define DK     64
#define BS     (B_SZ * S_SZ)          // 4096 rows

#define KTV_CHUNKS 16

// Scratch (no cudaMalloc allowed -> device globals)
__device__ float g_Q[BS * DM];
__device__ float g_K[BS * DM];
__device__ float g_V[BS * DM];
__device__ float g_O[BS * DM];
__device__ float g_M[B_SZ * NH * DK * DK];                 // (K^T V)/8 per (b,h)
__device__ float g_Mpart[B_SZ * NH][KTV_CHUNKS][DK * DK];  // partials (deterministic reduce)

// ---------------------------------------------------------------------------
// tf32 tensor-core GEMM: C[M,N] = A[M,K] * W[N,K]^T  (row-major, K contiguous)
// 128x128x32 tile, 256 threads = 8 warps (4 m x 2 n), warp tile 32x64,
// mma.sync.aligned.m16n8k8.row.col.f32.tf32.tf32.f32
// ---------------------------------------------------------------------------
#define GBM 128
#define GBN 128
#define GBK 32
#define SPAD 36   // 36-float row stride -> fragment LDS bank = (4g+t)%32, conflict-free

__device__ __forceinline__ uint32_t f2tf32(float f) {
    uint32_t r;
    asm("cvt.rna.tf32.f32 %0, %1;" : "=r"(r) : "f"(f));
    return r;
}

__device__ __forceinline__ void mma_tf32(float* c, const uint32_t* a, const uint32_t* b) {
    asm volatile(
        "mma.sync.aligned.m16n8k8.row.col.f32.tf32.tf32.f32 "
        "{%0,%1,%2,%3}, {%4,%5,%6,%7}, {%8,%9}, {%0,%1,%2,%3};\n"
        : "+f"(c[0]), "+f"(c[1]), "+f"(c[2]), "+f"(c[3])
        : "r"(a[0]), "r"(a[1]), "r"(a[2]), "r"(a[3]), "r"(b[0]), "r"(b[1]));
}

__global__ __launch_bounds__(256, 2)
void tf32gemm_nt(const float* __restrict__ A, const float* __restrict__ W,
                 float* __restrict__ C, int M, int N, int K)
{
    __shared__ uint32_t As[GBM][SPAD];
    __shared__ uint32_t Ws[GBN][SPAD];

    const int tid  = threadIdx.x;
    const int lane = tid & 31;
    const int wid  = tid >> 5;
    const int g    = lane >> 2;      // groupID 0..7
    const int t    = lane & 3;       // thread-in-group 0..3
    const int wm   = wid >> 1;       // 0..3
    const int wn   = wid & 1;        // 0..1

    const int bm = blockIdx.y * GBM;
    const int bn = blockIdx.x * GBN;

    // global-load mapping: 128 rows x 32 cols = 1024 float4; 4 per thread
    const int lr = tid >> 1;              // unused pattern replaced below
    (void)lr;

    float acc[2][8][4];
#pragma unroll
    for (int mi = 0; mi < 2; ++mi)
#pragma unroll
        for (int ni = 0; ni < 8; ++ni)
#pragma unroll
            for (int e = 0; e < 4; ++e) acc[mi][ni][e] = 0.0f;

    for (int k0 = 0; k0 < K; k0 += GBK) {
        // ---- global loads into registers ----
        float4 av[4], wv[4];
#pragma unroll
        for (int i = 0; i < 4; ++i) {
            int idx = tid + i * 256;       // 0..1023
            int r = idx >> 3;              // 0..127
            int c = (idx & 7) * 4;         // 0..28
            av[i] = *reinterpret_cast<const float4*>(&A[(size_t)(bm + r) * K + k0 + c]);
            wv[i] = *reinterpret_cast<const float4*>(&W[(size_t)(bn + r) * K + k0 + c]);
        }
        __syncthreads();   // previous tile fully consumed
        // ---- convert to tf32, store to smem ----
#pragma unroll
        for (int i = 0; i < 4; ++i) {
            int idx = tid + i * 256;
            int r = idx >> 3;
            int c = (idx & 7) * 4;
            uint4 at = {f2tf32(av[i].x), f2tf32(av[i].y), f2tf32(av[i].z), f2tf32(av[i].w)};
            uint4 wt = {f2tf32(wv[i].x), f2tf32(wv[i].y), f2tf32(wv[i].z), f2tf32(wv[i].w)};
            *reinterpret_cast<uint4*>(&As[r][c]) = at;
            *reinterpret_cast<uint4*>(&Ws[r][c]) = wt;
        }
        __syncthreads();

        // ---- compute: 4 k-steps of 8 ----
#pragma unroll
        for (int ks = 0; ks < 4; ++ks) {
            const int kk = ks * 8;
            uint32_t af[2][4];
#pragma unroll
            for (int mi = 0; mi < 2; ++mi) {
                int m = wm * 32 + mi * 16 + g;
                af[mi][0] = As[m][kk + t];
                af[mi][1] = As[m + 8][kk + t];
                af[mi][2] = As[m][kk + t + 4];
                af[mi][3] = As[m + 8][kk + t + 4];
            }
            uint32_t bf[8][2];
#pragma unroll
            for (int ni = 0; ni < 8; ++ni) {
                int n = wn * 64 + ni * 8 + g;
                bf[ni][0] = Ws[n][kk + t];
                bf[ni][1] = Ws[n][kk + t + 4];
            }
#pragma unroll
            for (int mi = 0; mi < 2; ++mi)
#pragma unroll
                for (int ni = 0; ni < 8; ++ni)
                    mma_tf32(acc[mi][ni], af[mi], bf[ni]);
        }
    }

    // ---- epilogue ----
#pragma unroll
    for (int mi = 0; mi < 2; ++mi) {
#pragma unroll
        for (int ni = 0; ni < 8; ++ni) {
            int row = bm + wm * 32 + mi * 16 + g;
            int col = bn + wn * 64 + ni * 8 + 2 * t;
            *reinterpret_cast<float2*>(&C[(size_t)row * N + col]) =
                make_float2(acc[mi][ni][0], acc[mi][ni][1]);
            *reinterpret_cast<float2*>(&C[(size_t)(row + 8) * N + col]) =
                make_float2(acc[mi][ni][2], acc[mi][ni][3]);
        }
    }
}

// ---------------------------------------------------------------------------
// ktv partial: P[bh][chunk][d1][d2] = sum_{s in chunk} K[b,s,h,d1]*V[b,s,h,d2]
// grid (KTV_CHUNKS, 32), 256 threads; each chunk = 128 seq rows
// ---------------------------------------------------------------------------
__global__ __launch_bounds__(256)
void ktv_partial(const float* __restrict__ Km, const float* __restrict__ Vm)
{
    const int chunk = blockIdx.x;
    const int bh = blockIdx.y;
    const int b = bh >> 4, h = bh & 15;
    const int sbase = chunk * (S_SZ / KTV_CHUNKS);
    const float* Kb = Km + (size_t)b * S_SZ * DM + h * DK;
    const float* Vb = Vm + (size_t)b * S_SZ * DM + h * DK;

    __shared__ float Ks[32][DK];
    __shared__ float Vs[32][DK];

    const int tid = threadIdx.x;
    const int tx = tid & 15;
    const int ty = tid >> 4;

    float acc[4][4];
#pragma unroll
    for (int i = 0; i < 4; ++i)
#pragma unroll
        for (int j = 0; j < 4; ++j) acc[i][j] = 0.0f;

    for (int s0 = sbase; s0 < sbase + S_SZ / KTV_CHUNKS; s0 += 32) {
#pragma unroll
        for (int i = 0; i < 2; ++i) {
            int idx = tid + i * 256;
            int r = idx >> 4;
            int c = (idx & 15) * 4;
            *reinterpret_cast<float4*>(&Ks[r][c]) =
                *reinterpret_cast<const float4*>(&Kb[(size_t)(s0 + r) * DM + c]);
            *reinterpret_cast<float4*>(&Vs[r][c]) =
                *reinterpret_cast<const float4*>(&Vb[(size_t)(s0 + r) * DM + c]);
        }
        __syncthreads();
#pragma unroll 8
        for (int s = 0; s < 32; ++s) {
            float kv[4], vv[4];
#pragma unroll
            for (int i = 0; i < 4; ++i) kv[i] = Ks[s][ty * 4 + i];
#pragma unroll
            for (int j = 0; j < 4; ++j) vv[j] = Vs[s][tx * 4 + j];
#pragma unroll
            for (int i = 0; i < 4; ++i)
#pragma unroll
                for (int j = 0; j < 4; ++j)
                    acc[i][j] = fmaf(kv[i], vv[j], acc[i][j]);
        }
        __syncthreads();
    }

    float* Pp = g_Mpart[bh][chunk];
#pragma unroll
    for (int i = 0; i < 4; ++i)
#pragma unroll
        for (int j = 0; j < 4; ++j)
            Pp[(ty * 4 + i) * DK + tx * 4 + j] = acc[i][j];
}

// deterministic reduce: M = 0.125 * sum_chunks P
__global__ __launch_bounds__(256)
void ktv_reduce(float* __restrict__ Mh)
{
    int o = blockIdx.x * 256 + threadIdx.x;      // < 32*4096
    int bh = o >> 12;
    int i = o & 4095;
    float s = 0.0f;
#pragma unroll
    for (int c = 0; c < KTV_CHUNKS; ++c) s += g_Mpart[bh][c][i];
    Mh[o] = s * 0.125f;
}

// ---------------------------------------------------------------------------
// qm: O[b,s,h*64+d2] = sum_d1 Q[b,s,h*64+d1] * M[bh][d1][d2]
// ---------------------------------------------------------------------------
__global__ __launch_bounds__(256)
void qm_kernel(const float* __restrict__ Q, const float* __restrict__ Mh,
               float* __restrict__ O)
{
    const int bh = blockIdx.y;
    const int b = bh >> 4, h = bh & 15;
    const int s0 = blockIdx.x * 64;

    __shared__ float Ms[DK][DK];
    __shared__ float Qs[64][DK];

    const float* Qb = Q + (size_t)b * S_SZ * DM + h * DK;
    const float* Mp = Mh + (size_t)bh * DK * DK;

    const int tid = threadIdx.x;
#pragma unroll
    for (int i = 0; i < 4; ++i) {
        int idx = tid + i * 256;
        int r = idx >> 4;
        int c = (idx & 15) * 4;
        *reinterpret_cast<float4*>(&Ms[r][c]) =
            *reinterpret_cast<const float4*>(&Mp[r * DK + c]);
        *reinterpret_cast<float4*>(&Qs[r][c]) =
            *reinterpret_cast<const float4*>(&Qb[(size_t)(s0 + r) * DM + c]);
    }
    __syncthreads();

    const int tx = tid & 15;
    const int ty = tid >> 4;
    float acc[4][4];
#pragma unroll
    for (int i = 0; i < 4; ++i)
#pragma unroll
        for (int j = 0; j < 4; ++j) acc[i][j] = 0.0f;

#pragma unroll 8
    for (int d = 0; d < DK; ++d) {
        float qv[4], mv[4];
#pragma unroll
        for (int i = 0; i < 4; ++i) qv[i] = Qs[ty * 4 + i][d];
#pragma unroll
        for (int j = 0; j < 4; ++j) mv[j] = Ms[d][tx * 4 + j];
#pragma unroll
        for (int i = 0; i < 4; ++i)
#pragma unroll
            for (int j = 0; j < 4; ++j)
                acc[i][j] = fmaf(qv[i], mv[j], acc[i][j]);
    }

    float* Op = O + (size_t)b * S_SZ * DM + (size_t)s0 * DM + h * DK;
#pragma unroll
    for (int i = 0; i < 4; ++i)
#pragma unroll
        for (int j = 0; j < 4; ++j)
            Op[(size_t)(ty * 4 + i) * DM + tx * 4 + j] = acc[i][j];
}

// ---------------------------------------------------------------------------
// Launch
// ---------------------------------------------------------------------------
extern "C" void kernel_launch(void* const* d_in, const int* in_sizes, int n_in,
                              void* d_out, int out_size)
{
    const float* query = (const float*)d_in[0];
    const float* key   = (const float*)d_in[1];
    const float* value = (const float*)d_in[2];
    // d_in[3] = mask (unused by reference)
    const float* Wq = (const float*)d_in[4];
    const float* Wk = (const float*)d_in[5];
    const float* Wv = (const float*)d_in[6];
    const float* Wo = (const float*)d_in[7];
    float* out = (float*)d_out;

    float *pQ, *pK, *pV, *pO, *pM;
    cudaGetSymbolAddress((void**)&pQ, g_Q);
    cudaGetSymbolAddress((void**)&pK, g_K);
    cudaGetSymbolAddress((void**)&pV, g_V);
    cudaGetSymbolAddress((void**)&pO, g_O);
    cudaGetSymbolAddress((void**)&pM, g_M);

    dim3 gridP(DM / GBN, BS / GBM);   // (8, 32)
    dim3 blk(256);

    // Projections on tensor cores (tf32)
    tf32gemm_nt<<<gridP, blk>>>(query, Wq, pQ, BS, DM, DM);
    tf32gemm_nt<<<gridP, blk>>>(key,   Wk, pK, BS, DM, DM);
    tf32gemm_nt<<<gridP, blk>>>(value, Wv, pV, BS, DM, DM);

    // M = (K^T V)/8 per (b,h): split over S for parallelism, deterministic reduce
    dim3 gridKTV(KTV_CHUNKS, B_SZ * NH);
    ktv_partial<<<gridKTV, blk>>>(pK, pV);
    ktv_reduce<<<(B_SZ * NH * DK * DK) / 256, blk>>>(pM);

    // O = Q M per (b,h)
    dim3 gridQM(S_SZ / 64, B_SZ * NH);
    qm_kernel<<<gridQM, blk>>>(pQ, pM, pO);

    // final = O Wo^T
    tf32gemm_nt<<<gridP, blk>>>(pO, Wo, out, BS, DM, DM);
}

// round 4
// speedup vs baseline: 3.5020x; 1.0566x over previous
#include <cuda_runtime.h>
#include <cuda_bf16.h>
#include <cstdint>

// Problem constants
#define B_SZ   2
#define S_SZ   2048
#define DM     1024
#define NH     16
#define DK     64
#define BS     (B_SZ * S_SZ)          // 4096 rows

#define KTV_CHUNKS 32

// Scratch (no cudaMalloc allowed -> device globals)
__device__ float g_Q[BS * DM];
__device__ float g_K[BS * DM];
__device__ float g_V[BS * DM];
__device__ float g_O[BS * DM];
__device__ float g_M[B_SZ * NH * DK * DK];                 // (K^T V)/8 per (b,h)
__device__ float g_Mpart[B_SZ * NH][KTV_CHUNKS][DK * DK];  // partials (deterministic reduce)

// ---------------------------------------------------------------------------
// tf32 tensor-core GEMM: C[M,N] = A[M,K] * W[N,K]^T  (row-major, K contiguous)
// 128x128x32 tile, 256 threads = 8 warps (4m x 2n), warp tile 32x64,
// double-buffered smem (dynamic, 2 stages), one __syncthreads per k-tile.
// ---------------------------------------------------------------------------
#define GBM 128
#define GBN 128
#define GBK 32
#define SPAD 36   // 36-word row stride -> fragment LDS bank = (4g+t)%32, conflict-free
#define GEMM_SMEM_BYTES (2 * 2 * GBM * SPAD * 4)   // 73728

__device__ __forceinline__ uint32_t f2tf32(float f) {
    uint32_t r;
    asm("cvt.rna.tf32.f32 %0, %1;" : "=r"(r) : "f"(f));
    return r;
}

__device__ __forceinline__ void mma_tf32(float* c, const uint32_t* a, const uint32_t* b) {
    asm volatile(
        "mma.sync.aligned.m16n8k8.row.col.f32.tf32.tf32.f32 "
        "{%0,%1,%2,%3}, {%4,%5,%6,%7}, {%8,%9}, {%0,%1,%2,%3};\n"
        : "+f"(c[0]), "+f"(c[1]), "+f"(c[2]), "+f"(c[3])
        : "r"(a[0]), "r"(a[1]), "r"(a[2]), "r"(a[3]), "r"(b[0]), "r"(b[1]));
}

__device__ __forceinline__
void gemm_body(const float* __restrict__ A, const float* __restrict__ W,
               float* __restrict__ C, int M, int N, int K,
               int bm, int bn)
{
    extern __shared__ uint32_t sm[];
    // layout: As[2][128][SPAD], Ws[2][128][SPAD]
    uint32_t (*As)[SPAD] = reinterpret_cast<uint32_t (*)[SPAD]>(sm);
    uint32_t (*Ws)[SPAD] = reinterpret_cast<uint32_t (*)[SPAD]>(sm + 2 * GBM * SPAD);

    const int tid  = threadIdx.x;
    const int lane = tid & 31;
    const int wid  = tid >> 5;
    const int g    = lane >> 2;      // 0..7
    const int t    = lane & 3;       // 0..3
    const int wm   = wid >> 1;       // 0..3
    const int wn   = wid & 1;        // 0..1

    // global-load mapping: 128 rows x 32 cols = 1024 float4; 4 per thread
    const int lr = tid >> 3;              // 0..31 base row step handled below
    const int lc = (tid & 7) * 4;         // 0..28
    (void)lr;

    float acc[2][8][4];
#pragma unroll
    for (int mi = 0; mi < 2; ++mi)
#pragma unroll
        for (int ni = 0; ni < 8; ++ni)
#pragma unroll
            for (int e = 0; e < 4; ++e) acc[mi][ni][e] = 0.0f;

    float4 av[4], wv[4];

    // ---- prologue: load + store tile 0 ----
#pragma unroll
    for (int i = 0; i < 4; ++i) {
        int idx = tid + i * 256;
        int r = idx >> 3;
        int c = (idx & 7) * 4;
        av[i] = *reinterpret_cast<const float4*>(&A[(size_t)(bm + r) * K + c]);
        wv[i] = *reinterpret_cast<const float4*>(&W[(size_t)(bn + r) * K + c]);
    }
#pragma unroll
    for (int i = 0; i < 4; ++i) {
        int idx = tid + i * 256;
        int r = idx >> 3;
        int c = (idx & 7) * 4;
        uint4 at = {f2tf32(av[i].x), f2tf32(av[i].y), f2tf32(av[i].z), f2tf32(av[i].w)};
        uint4 wt = {f2tf32(wv[i].x), f2tf32(wv[i].y), f2tf32(wv[i].z), f2tf32(wv[i].w)};
        *reinterpret_cast<uint4*>(&As[r][c]) = at;
        *reinterpret_cast<uint4*>(&Ws[r][c]) = wt;
    }
    __syncthreads();

    const int NT = K / GBK;
    for (int kt = 0; kt < NT; ++kt) {
        const int cur = kt & 1;
        // ---- issue global loads for next tile (hidden under compute) ----
        if (kt + 1 < NT) {
            const int k0 = (kt + 1) * GBK;
#pragma unroll
            for (int i = 0; i < 4; ++i) {
                int idx = tid + i * 256;
                int r = idx >> 3;
                int c = (idx & 7) * 4;
                av[i] = *reinterpret_cast<const float4*>(&A[(size_t)(bm + r) * K + k0 + c]);
                wv[i] = *reinterpret_cast<const float4*>(&W[(size_t)(bn + r) * K + k0 + c]);
            }
        }

        // ---- compute on current buffer: 4 k-steps of 8 ----
        const uint32_t (*Ab)[SPAD] = As + cur * GBM;
        const uint32_t (*Wb)[SPAD] = Ws + cur * GBM;
#pragma unroll
        for (int ks = 0; ks < 4; ++ks) {
            const int kk = ks * 8;
            uint32_t af[2][4];
#pragma unroll
            for (int mi = 0; mi < 2; ++mi) {
                int m = wm * 32 + mi * 16 + g;
                af[mi][0] = Ab[m][kk + t];
                af[mi][1] = Ab[m + 8][kk + t];
                af[mi][2] = Ab[m][kk + t + 4];
                af[mi][3] = Ab[m + 8][kk + t + 4];
            }
            uint32_t bf[8][2];
#pragma unroll
            for (int ni = 0; ni < 8; ++ni) {
                int n = wn * 64 + ni * 8 + g;
                bf[ni][0] = Wb[n][kk + t];
                bf[ni][1] = Wb[n][kk + t + 4];
            }
#pragma unroll
            for (int mi = 0; mi < 2; ++mi)
#pragma unroll
                for (int ni = 0; ni < 8; ++ni)
                    mma_tf32(acc[mi][ni], af[mi], bf[ni]);
        }

        // ---- store next tile into the other buffer ----
        if (kt + 1 < NT) {
            const int nxt = (kt + 1) & 1;
#pragma unroll
            for (int i = 0; i < 4; ++i) {
                int idx = tid + i * 256;
                int r = idx >> 3;
                int c = (idx & 7) * 4;
                uint4 at = {f2tf32(av[i].x), f2tf32(av[i].y), f2tf32(av[i].z), f2tf32(av[i].w)};
                uint4 wt = {f2tf32(wv[i].x), f2tf32(wv[i].y), f2tf32(wv[i].z), f2tf32(wv[i].w)};
                *reinterpret_cast<uint4*>(&As[nxt * GBM + r][c]) = at;
                *reinterpret_cast<uint4*>(&Ws[nxt * GBM + r][c]) = wt;
            }
            __syncthreads();
        }
    }

    // ---- epilogue ----
#pragma unroll
    for (int mi = 0; mi < 2; ++mi) {
#pragma unroll
        for (int ni = 0; ni < 8; ++ni) {
            int row = bm + wm * 32 + mi * 16 + g;
            int col = bn + wn * 64 + ni * 8 + 2 * t;
            *reinterpret_cast<float2*>(&C[(size_t)row * N + col]) =
                make_float2(acc[mi][ni][0], acc[mi][ni][1]);
            *reinterpret_cast<float2*>(&C[(size_t)(row + 8) * N + col]) =
                make_float2(acc[mi][ni][2], acc[mi][ni][3]);
        }
    }
}

// Merged Q/K/V projection: blockIdx.z selects which projection
__global__ __launch_bounds__(256, 2)
void qkv_gemm(const float* __restrict__ q, const float* __restrict__ k,
              const float* __restrict__ v,
              const float* __restrict__ Wq, const float* __restrict__ Wk,
              const float* __restrict__ Wv)
{
    const float* A;
    const float* W;
    float* C;
    if (blockIdx.z == 0)      { A = q; W = Wq; C = g_Q; }
    else if (blockIdx.z == 1) { A = k; W = Wk; C = g_K; }
    else                      { A = v; W = Wv; C = g_V; }
    gemm_body(A, W, C, BS, DM, DM, blockIdx.y * GBM, blockIdx.x * GBN);
}

__global__ __launch_bounds__(256, 2)
void out_gemm(const float* __restrict__ Wo, float* __restrict__ out)
{
    gemm_body(g_O, Wo, out, BS, DM, DM, blockIdx.y * GBM, blockIdx.x * GBN);
}

// ---------------------------------------------------------------------------
// ktv partial: P[bh][chunk][d1][d2] = sum_{s in chunk} K[b,s,h,d1]*V[b,s,h,d2]
// grid (KTV_CHUNKS, 32), 256 threads; each chunk = 64 seq rows
// ---------------------------------------------------------------------------
__global__ __launch_bounds__(256)
void ktv_partial(const float* __restrict__ Km, const float* __restrict__ Vm)
{
    const int chunk = blockIdx.x;
    const int bh = blockIdx.y;
    const int b = bh >> 4, h = bh & 15;
    const int sbase = chunk * (S_SZ / KTV_CHUNKS);
    const float* Kb = Km + (size_t)b * S_SZ * DM + h * DK;
    const float* Vb = Vm + (size_t)b * S_SZ * DM + h * DK;

    __shared__ float Ks[32][DK];
    __shared__ float Vs[32][DK];

    const int tid = threadIdx.x;
    const int tx = tid & 15;
    const int ty = tid >> 4;

    float acc[4][4];
#pragma unroll
    for (int i = 0; i < 4; ++i)
#pragma unroll
        for (int j = 0; j < 4; ++j) acc[i][j] = 0.0f;

    for (int s0 = sbase; s0 < sbase + S_SZ / KTV_CHUNKS; s0 += 32) {
#pragma unroll
        for (int i = 0; i < 2; ++i) {
            int idx = tid + i * 256;
            int r = idx >> 4;
            int c = (idx & 15) * 4;
            *reinterpret_cast<float4*>(&Ks[r][c]) =
                *reinterpret_cast<const float4*>(&Kb[(size_t)(s0 + r) * DM + c]);
            *reinterpret_cast<float4*>(&Vs[r][c]) =
                *reinterpret_cast<const float4*>(&Vb[(size_t)(s0 + r) * DM + c]);
        }
        __syncthreads();
#pragma unroll 8
        for (int s = 0; s < 32; ++s) {
            float4 kv = *reinterpret_cast<const float4*>(&Ks[s][ty * 4]);
            float4 vv = *reinterpret_cast<const float4*>(&Vs[s][tx * 4]);
            float ka[4] = {kv.x, kv.y, kv.z, kv.w};
            float va[4] = {vv.x, vv.y, vv.z, vv.w};
#pragma unroll
            for (int i = 0; i < 4; ++i)
#pragma unroll
                for (int j = 0; j < 4; ++j)
                    acc[i][j] = fmaf(ka[i], va[j], acc[i][j]);
        }
        __syncthreads();
    }

    float* Pp = g_Mpart[bh][chunk];
#pragma unroll
    for (int i = 0; i < 4; ++i)
#pragma unroll
        for (int j = 0; j < 4; ++j)
            Pp[(ty * 4 + i) * DK + tx * 4 + j] = acc[i][j];
}

// deterministic reduce: M = 0.125 * sum_chunks P
__global__ __launch_bounds__(256)
void ktv_reduce(float* __restrict__ Mh)
{
    int o = blockIdx.x * 256 + threadIdx.x;      // < 32*4096
    int bh = o >> 12;
    int i = o & 4095;
    float s = 0.0f;
#pragma unroll
    for (int c = 0; c < KTV_CHUNKS; ++c) s += g_Mpart[bh][c][i];
    Mh[o] = s * 0.125f;
}

// ---------------------------------------------------------------------------
// qm: O[b,s,h*64+d2] = sum_d1 Q[b,s,h*64+d1] * M[bh][d1][d2]
// grid (32, 32), 256 threads; 64x64 tile; float4 inner loop
// ---------------------------------------------------------------------------
__global__ __launch_bounds__(256)
void qm_kernel(const float* __restrict__ Q, const float* __restrict__ Mh,
               float* __restrict__ O)
{
    const int bh = blockIdx.y;
    const int b = bh >> 4, h = bh & 15;
    const int s0 = blockIdx.x * 64;

    __shared__ float Ms[DK][DK];
    __shared__ float Qs[64][DK];

    const float* Qb = Q + (size_t)b * S_SZ * DM + h * DK;
    const float* Mp = Mh + (size_t)bh * DK * DK;

    const int tid = threadIdx.x;
#pragma unroll
    for (int i = 0; i < 4; ++i) {
        int idx = tid + i * 256;
        int r = idx >> 4;
        int c = (idx & 15) * 4;
        *reinterpret_cast<float4*>(&Ms[r][c]) =
            *reinterpret_cast<const float4*>(&Mp[r * DK + c]);
        *reinterpret_cast<float4*>(&Qs[r][c]) =
            *reinterpret_cast<const float4*>(&Qb[(size_t)(s0 + r) * DM + c]);
    }
    __syncthreads();

    const int tx = tid & 15;
    const int ty = tid >> 4;
    float acc[4][4];
#pragma unroll
    for (int i = 0; i < 4; ++i)
#pragma unroll
        for (int j = 0; j < 4; ++j) acc[i][j] = 0.0f;

#pragma unroll 4
    for (int d = 0; d < DK; d += 4) {
        float4 qv[4], mv[4];
#pragma unroll
        for (int i = 0; i < 4; ++i)
            qv[i] = *reinterpret_cast<const float4*>(&Qs[ty * 4 + i][d]);
#pragma unroll
        for (int e = 0; e < 4; ++e)
            mv[e] = *reinterpret_cast<const float4*>(&Ms[d + e][tx * 4]);
#pragma unroll
        for (int i = 0; i < 4; ++i) {
            float qa[4] = {qv[i].x, qv[i].y, qv[i].z, qv[i].w};
#pragma unroll
            for (int e = 0; e < 4; ++e) {
                acc[i][0] = fmaf(qa[e], mv[e].x, acc[i][0]);
                acc[i][1] = fmaf(qa[e], mv[e].y, acc[i][1]);
                acc[i][2] = fmaf(qa[e], mv[e].z, acc[i][2]);
                acc[i][3] = fmaf(qa[e], mv[e].w, acc[i][3]);
            }
        }
    }

    float* Op = O + (size_t)b * S_SZ * DM + (size_t)s0 * DM + h * DK;
#pragma unroll
    for (int i = 0; i < 4; ++i) {
        float4 v = {acc[i][0], acc[i][1], acc[i][2], acc[i][3]};
        *reinterpret_cast<float4*>(&Op[(size_t)(ty * 4 + i) * DM + tx * 4]) = v;
    }
}

// ---------------------------------------------------------------------------
// Launch
// ---------------------------------------------------------------------------
extern "C" void kernel_launch(void* const* d_in, const int* in_sizes, int n_in,
                              void* d_out, int out_size)
{
    const float* query = (const float*)d_in[0];
    const float* key   = (const float*)d_in[1];
    const float* value = (const float*)d_in[2];
    // d_in[3] = mask (unused by reference)
    const float* Wq = (const float*)d_in[4];
    const float* Wk = (const float*)d_in[5];
    const float* Wv = (const float*)d_in[6];
    const float* Wo = (const float*)d_in[7];
    float* out = (float*)d_out;

    float *pQ, *pK, *pV, *pO, *pM;
    cudaGetSymbolAddress((void**)&pQ, g_Q);
    cudaGetSymbolAddress((void**)&pK, g_K);
    cudaGetSymbolAddress((void**)&pV, g_V);
    cudaGetSymbolAddress((void**)&pO, g_O);
    cudaGetSymbolAddress((void**)&pM, g_M);

    static bool attr_done = false;
    if (!attr_done) {
        cudaFuncSetAttribute(qkv_gemm, cudaFuncAttributeMaxDynamicSharedMemorySize,
                             GEMM_SMEM_BYTES);
        cudaFuncSetAttribute(out_gemm, cudaFuncAttributeMaxDynamicSharedMemorySize,
                             GEMM_SMEM_BYTES);
        attr_done = true;
    }

    dim3 blk(256);

    // Q/K/V projections (tf32 tensor cores, double-buffered), merged launch
    dim3 gridQKV(DM / GBN, BS / GBM, 3);   // (8, 32, 3)
    qkv_gemm<<<gridQKV, blk, GEMM_SMEM_BYTES>>>(query, key, value, Wq, Wk, Wv);

    // M = (K^T V)/8 per (b,h): split over S, deterministic reduce
    dim3 gridKTV(KTV_CHUNKS, B_SZ * NH);
    ktv_partial<<<gridKTV, blk>>>(pK, pV);
    ktv_reduce<<<(B_SZ * NH * DK * DK) / 256, blk>>>(pM);

    // O = Q M per (b,h)
    dim3 gridQM(S_SZ / 64, B_SZ * NH);
    qm_kernel<<<gridQM, blk>>>(pQ, pM, pO);

    // final = O Wo^T
    dim3 gridO(DM / GBN, BS / GBM, 1);
    out_gemm<<<gridO, blk, GEMM_SMEM_BYTES>>>(Wo, out);
}